// round 11
// baseline (speedup 1.0000x reference)
#include <cuda_runtime.h>
#include <cstdint>

#define BB 2048
#define SC 64                   // rows per chunk
#define NCH 8
#define ASTR 68                 // A row stride in words (64 + 4 pad, bank-safe)
#define ABYTES (SC * ASTR * 4)  // 17408 per buffer

// smem byte offsets (all dynamic)
#define OFF_A    0
#define OFF_B    34816                  // packed B: 8 KB
#define OFF_PART 43008                  // [2][64]
#define OFF_CTXP 43520                  // [8][64]
#define OFF_CTXA 45568
#define OFF_S    45824
#define OFF_PRE  45952
#define OFF_V    46080
#define OFF_GH   46208
#define OFF_GIE  46592
#define OFF_EMB  46976
#define OFF_RED  47040
#define OFF_LSUM 47072
#define SMEM_SZ  47088                  // x4 CTAs = 188 KB/SM

__device__ __forceinline__ uint32_t smem_u32(const void* p) {
    uint32_t a;
    asm("{ .reg .u64 t; cvta.to.shared.u64 t, %1; cvt.u32.u64 %0, t; }" : "=r"(a) : "l"(p));
    return a;
}
__device__ __forceinline__ uint32_t f2tf32(float x) {
    uint32_t r; asm("cvt.rna.tf32.f32 %0, %1;" : "=r"(r) : "f"(x)); return r;
}
__device__ __forceinline__ float tanh_ap(float x) {
    float y; asm("tanh.approx.f32 %0, %1;" : "=f"(y) : "f"(x)); return y;
}
__device__ __forceinline__ float sigm(float x) { return 1.0f / (1.0f + __expf(-x)); }

__device__ __forceinline__ void cpasync16(uint32_t dst, const void* src) {
    asm volatile("cp.async.cg.shared.global [%0], [%1], 16;" :: "r"(dst), "l"(src) : "memory");
}
__device__ __forceinline__ void cp_commit() {
    asm volatile("cp.async.commit_group;" ::: "memory");
}
__device__ __forceinline__ void cp_wait0() {
    asm volatile("cp.async.wait_group 0;" ::: "memory");
}
__device__ __forceinline__ void barpair(int id) {
    asm volatile("bar.sync %0, 64;" :: "r"(id) : "memory");
}
__device__ __forceinline__ void mma_tf32(float* d, const uint32_t* a, uint32_t b0, uint32_t b1) {
    asm volatile(
        "mma.sync.aligned.m16n8k8.row.col.f32.tf32.tf32.f32 "
        "{%0,%1,%2,%3}, {%4,%5,%6,%7}, {%8,%9}, {%0,%1,%2,%3};"
        : "+f"(d[0]), "+f"(d[1]), "+f"(d[2]), "+f"(d[3])
        : "r"(a[0]), "r"(a[1]), "r"(a[2]), "r"(a[3]), "r"(b0), "r"(b1));
}

__global__ __launch_bounds__(256, 4) void decoder_occ4_kernel(
    const float* __restrict__ dec_in, const float* __restrict__ s_in,
    const float* __restrict__ enc,    const float* __restrict__ W_attn,
    const float* __restrict__ b_attn, const float* __restrict__ v_attn,
    const float* __restrict__ W_emb,  const float* __restrict__ b_emb,
    const float* __restrict__ W_ih,   const float* __restrict__ W_hh,
    const float* __restrict__ b_ih,   const float* __restrict__ b_hh,
    const float* __restrict__ W_fc,   const float* __restrict__ b_fc,
    float* __restrict__ out, int write_h)
{
    extern __shared__ __align__(16) unsigned char sm[];
    float*    Asf    = (float*)(sm + OFF_A);
    uint32_t* Bw     = (uint32_t*)(sm + OFF_B);
    float*    part   = (float*)(sm + OFF_PART);
    float*    ctxp   = (float*)(sm + OFF_CTXP);
    float*    ctxa   = (float*)(sm + OFF_CTXA);
    float*    s_sm   = (float*)(sm + OFF_S);
    float*    pre_sm = (float*)(sm + OFF_PRE);
    float*    v_sm2  = (float*)(sm + OFF_V);
    float*    gh_sm  = (float*)(sm + OFF_GH);
    float*    gie_sm = (float*)(sm + OFF_GIE);
    float*    emb_sm = (float*)(sm + OFF_EMB);
    float*    red    = (float*)(sm + OFF_RED);
    float*    lsum   = (float*)(sm + OFF_LSUM);

    const int t    = threadIdx.x;
    const int b    = blockIdx.x;
    const int lane = t & 31;
    const int w    = t >> 5;
    const int qid  = lane >> 2;
    const int qtr  = lane & 3;
    const uint32_t su = smem_u32(sm);

    // staging map: thread covers rows rowg+16*it (it<4), 16-B segment seg
    const int rowg = t >> 4;            // 0..15
    const int seg  = t & 15;            // 0..15
    const float* gbase = enc + ((size_t)rowg * BB + b) * 64 + seg * 4;
    const uint32_t sbase = su + OFF_A + (rowg * ASTR + seg * 4) * 4;
    const size_t gstep = (size_t)16 * BB * 64;   // 16 rows

    // ---- prologue: chunk 0 in flight ----
    {
        const float* g = gbase;
        uint32_t s = sbase;
        #pragma unroll
        for (int it = 0; it < 4; ++it) {
            cpasync16(s, g);
            g += gstep;
            s += 16 * ASTR * 4;
        }
        cp_commit();
    }

    // ---- init / precompute (overlaps stream) ----
    if (t < 32) s_sm[t] = s_in[b * 32 + t];
    if (t < 16) {
        float e = W_emb[t] * dec_in[b] + b_emb[t];
        emb_sm[t] = e > 0.f ? e : 0.f;
    }
    // packed B: word idx = entry*2 + slot; entry = ks*128 + cg*32 + qtr*8 + qid
    // value = tf32(W_attn[j*96 + 32 + k]) with k = 8ks + 4*slot + qtr, j = 8cg + qid
    for (int wdx = t; wdx < 2048; wdx += 256) {
        int e    = wdx >> 1;
        int slot = wdx & 1;
        int q    = e & 7;
        int r    = (e >> 3) & 3;
        int cg   = (e >> 5) & 3;
        int ks   = e >> 7;
        int k    = ks * 8 + slot * 4 + r;
        int j    = cg * 8 + q;
        Bw[wdx] = f2tf32(W_attn[j * 96 + 32 + k]);
    }
    __syncthreads();

    if (t < 32) {
        float a = b_attn[t];
        #pragma unroll
        for (int m = 0; m < 32; ++m) a += W_attn[t * 96 + m] * s_sm[m];
        pre_sm[t] = a;
        v_sm2[t]  = v_attn[t];
    } else if (t < 128) {
        int g = t - 32;
        float a = b_hh[g];
        #pragma unroll
        for (int m = 0; m < 32; ++m) a += W_hh[g * 32 + m] * s_sm[m];
        gh_sm[g] = a;
    } else if (t < 224) {
        int g = t - 128;
        float a = b_ih[g];
        #pragma unroll
        for (int m = 0; m < 16; ++m) a += W_ih[g * 80 + m] * emb_sm[m];
        gie_sm[g] = a;
    }
    __syncthreads();

    // warp tiling: rows m0..m0+15, cols [nhalf*16, nhalf*16+16)
    const int m0 = (w & 3) * 16;
    const int nhalf = w >> 2;           // 0 or 1
    const int nt0 = nhalf * 2;
    const int barid = 1 + (w & 3);
    const int ctxrow0 = m0 + nhalf * 8; // this warp's 8 ctx/exp rows

    // per-(ks) packed-B base for this thread's two column groups
    const uint2* Bp = (const uint2*)Bw;
    const int be0 = nt0 * 32 + qtr * 8 + qid;        // + ks*128 per step (cg=nt0)
    const int be1 = be0 + 32;                        // cg=nt0+1

    float preR[2][2], vR[2][2];
    #pragma unroll
    for (int i = 0; i < 2; ++i) {
        int c = (nt0 + i) * 8 + 2 * qtr;
        preR[i][0] = pre_sm[c];  preR[i][1] = pre_sm[c + 1];
        vR[i][0]   = v_sm2[c];   vR[i][1]   = v_sm2[c + 1];
    }

    float cacc0 = 0.f, cacc1 = 0.f, l_acc = 0.f;

    // ---------------- pipelined chunk loop ----------------
    for (int ch = 0; ch < NCH; ++ch) {
        cp_wait0();
        __syncthreads();               // chunk ch visible; prior ctx reads done

        if (ch < NCH - 1) {
            const float* g = gbase + (size_t)(ch + 1) * SC * (BB * 64);
            uint32_t s = sbase + ((ch + 1) & 1) * ABYTES;
            #pragma unroll
            for (int it = 0; it < 4; ++it) {
                cpasync16(s, g);
                g += gstep;
                s += 16 * ASTR * 4;
            }
            cp_commit();
        }

        const float* A = Asf + (ch & 1) * (SC * ASTR);
        const float* aptr = A + (m0 + qid) * ASTR + qtr;

        float D[2][4];
        #pragma unroll
        for (int i = 0; i < 2; ++i)
            #pragma unroll
            for (int k = 0; k < 4; ++k) D[i][k] = 0.f;

        #pragma unroll
        for (int ks = 0; ks < 8; ++ks) {
            uint32_t a[4];
            a[0] = f2tf32(aptr[8 * ks]);
            a[1] = f2tf32(aptr[8 * ASTR + 8 * ks]);
            a[2] = f2tf32(aptr[8 * ks + 4]);
            a[3] = f2tf32(aptr[8 * ASTR + 8 * ks + 4]);
            uint2 b0 = Bp[ks * 128 + be0];
            uint2 b1 = Bp[ks * 128 + be1];
            mma_tf32(D[0], a, b0.x, b0.y);
            mma_tf32(D[1], a, b1.x, b1.y);
        }

        // half-logit partials over this warp's 16 cols
        float pl0 = 0.f, pl1 = 0.f;
        #pragma unroll
        for (int i = 0; i < 2; ++i) {
            pl0 += vR[i][0] * tanh_ap(D[i][0] + preR[i][0]);
            pl0 += vR[i][1] * tanh_ap(D[i][1] + preR[i][1]);
            pl1 += vR[i][0] * tanh_ap(D[i][2] + preR[i][0]);
            pl1 += vR[i][1] * tanh_ap(D[i][3] + preR[i][1]);
        }
        pl0 += __shfl_xor_sync(0xffffffffu, pl0, 1);
        pl0 += __shfl_xor_sync(0xffffffffu, pl0, 2);
        pl1 += __shfl_xor_sync(0xffffffffu, pl1, 1);
        pl1 += __shfl_xor_sync(0xffffffffu, pl1, 2);
        if (qtr == 0) {
            part[nhalf * 64 + m0 + qid]     = pl0;
            part[nhalf * 64 + m0 + 8 + qid] = pl1;
        }
        barpair(barid);    // pair (w, w+4) exchanged half-logits

        // exp once per row (lanes 0..7), broadcast via shuffle into ctx loop
        float pexp = 0.f;
        if (lane < 8) {
            int row = ctxrow0 + lane;
            pexp = __expf(part[row] + part[64 + row]);   // |logit| <= ~1.3, safe
            l_acc += pexp;
        }
        #pragma unroll
        for (int rr = 0; rr < 8; ++rr) {
            float ps = __shfl_sync(0xffffffffu, pexp, rr);
            float2 e2 = *(const float2*)&A[(ctxrow0 + rr) * ASTR + 2 * lane];
            cacc0 += ps * e2.x;
            cacc1 += ps * e2.y;
        }
    }

    // ---------------- reductions ----------------
    ctxp[w * 64 + 2 * lane]     = cacc0;
    ctxp[w * 64 + 2 * lane + 1] = cacc1;
    {
        float ws = l_acc;   // only lanes 0..7 nonzero
        #pragma unroll
        for (int off = 16; off > 0; off >>= 1)
            ws += __shfl_xor_sync(0xffffffffu, ws, off);
        if (lane == 0) red[w] = ws;
    }
    __syncthreads();
    if (t == 0)
        lsum[0] = red[0] + red[1] + red[2] + red[3] +
                  red[4] + red[5] + red[6] + red[7];
    __syncthreads();
    if (t < 64) {
        float c = 0.f;
        #pragma unroll
        for (int ww = 0; ww < 8; ++ww) c += ctxp[ww * 64 + t];
        ctxa[t] = c / lsum[0];
    }
    __syncthreads();

    // ---------------- GRU + fc (warp 0) ----------------
    if (w == 0) {
        int j = lane;
        float gir = gie_sm[j], giz = gie_sm[32 + j], gin = gie_sm[64 + j];
        const float* wr = W_ih + j        * 80 + 16;
        const float* wz = W_ih + (32 + j) * 80 + 16;
        const float* wn = W_ih + (64 + j) * 80 + 16;
        #pragma unroll 8
        for (int k2 = 0; k2 < 64; ++k2) {
            float c = ctxa[k2];
            gir += wr[k2] * c;
            giz += wz[k2] * c;
            gin += wn[k2] * c;
        }
        float r = sigm(gir + gh_sm[j]);
        float z = sigm(giz + gh_sm[32 + j]);
        float n = tanhf(gin + r * gh_sm[64 + j]);
        float h = (1.f - z) * n + z * s_sm[j];
        if (write_h) out[BB + b * 32 + j] = h;

        float contrib = h * W_fc[j]
                      + ctxa[2 * j]     * W_fc[32 + 2 * j]
                      + ctxa[2 * j + 1] * W_fc[33 + 2 * j];
        if (j < 16) contrib += emb_sm[j] * W_fc[96 + j];
        #pragma unroll
        for (int off = 16; off > 0; off >>= 1)
            contrib += __shfl_xor_sync(0xffffffffu, contrib, off);
        if (j == 0) out[b] = contrib + b_fc[0];
    }
}

extern "C" void kernel_launch(void* const* d_in, const int* in_sizes, int n_in,
                              void* d_out, int out_size) {
    const float* dec_in = (const float*)d_in[0];
    const float* s_in   = (const float*)d_in[1];
    const float* enc    = (const float*)d_in[2];
    const float* W_attn = (const float*)d_in[3];
    const float* b_attn = (const float*)d_in[4];
    const float* v_attn = (const float*)d_in[5];
    const float* W_emb  = (const float*)d_in[6];
    const float* b_emb  = (const float*)d_in[7];
    const float* W_ih   = (const float*)d_in[8];
    const float* W_hh   = (const float*)d_in[9];
    const float* b_ih   = (const float*)d_in[10];
    const float* b_hh   = (const float*)d_in[11];
    const float* W_fc   = (const float*)d_in[12];
    const float* b_fc   = (const float*)d_in[13];

    cudaFuncSetAttribute(decoder_occ4_kernel,
                         cudaFuncAttributeMaxDynamicSharedMemorySize, SMEM_SZ);
    int write_h = (out_size >= BB * 33) ? 1 : 0;
    decoder_occ4_kernel<<<BB, 256, SMEM_SZ>>>(dec_in, s_in, enc, W_attn, b_attn, v_attn,
                                              W_emb, b_emb, W_ih, W_hh, b_ih, b_hh,
                                              W_fc, b_fc, (float*)d_out, write_h);
}

// round 14
// speedup vs baseline: 1.1617x; 1.1617x over previous
#include <cuda_runtime.h>
#include <cstdint>

#define BB 2048
#define SC 64                   // rows per chunk
#define NCH 8
#define ASTR 72                 // A row stride in words (64 + 8 pad; rowD==8 mod 32)
#define BSTR 36
#define ABYTES (SC * ASTR * 4)  // 18432 per buffer

// smem byte offsets (all dynamic)
#define OFF_A    0
#define OFF_B    36864                  // Bs staging 9216
#define OFF_PART 46080                  // [2][64]
#define OFF_CTXP 46592                  // [8][64]
#define OFF_CTXA 48640
#define OFF_S    48896
#define OFF_PRE  49024
#define OFF_V    49152
#define OFF_GH   49280
#define OFF_GIE  49664
#define OFF_EMB  50048
#define OFF_RED  50112
#define OFF_LSUM 50144
#define SMEM_SZ  50160                  // ~49 KB -> 3 CTAs/SM (reg-capped)

__device__ __forceinline__ uint32_t smem_u32(const void* p) {
    uint32_t a;
    asm("{ .reg .u64 t; cvta.to.shared.u64 t, %1; cvt.u32.u64 %0, t; }" : "=r"(a) : "l"(p));
    return a;
}
__device__ __forceinline__ uint32_t f2tf32(float x) {
    uint32_t r; asm("cvt.rna.tf32.f32 %0, %1;" : "=r"(r) : "f"(x)); return r;
}
__device__ __forceinline__ float tanh_ap(float x) {
    float y; asm("tanh.approx.f32 %0, %1;" : "=f"(y) : "f"(x)); return y;
}
__device__ __forceinline__ float sigm(float x) { return 1.0f / (1.0f + __expf(-x)); }

__device__ __forceinline__ void cpasync16(uint32_t dst, const void* src) {
    asm volatile("cp.async.cg.shared.global [%0], [%1], 16;" :: "r"(dst), "l"(src) : "memory");
}
__device__ __forceinline__ void cp_commit() {
    asm volatile("cp.async.commit_group;" ::: "memory");
}
__device__ __forceinline__ void cp_wait0() {
    asm volatile("cp.async.wait_group 0;" ::: "memory");
}
__device__ __forceinline__ void barpair(int id) {
    asm volatile("bar.sync %0, 64;" :: "r"(id) : "memory");
}
__device__ __forceinline__ void mma_tf32(float* d, const uint32_t* a, uint32_t b0, uint32_t b1) {
    asm volatile(
        "mma.sync.aligned.m16n8k8.row.col.f32.tf32.tf32.f32 "
        "{%0,%1,%2,%3}, {%4,%5,%6,%7}, {%8,%9}, {%0,%1,%2,%3};"
        : "+f"(d[0]), "+f"(d[1]), "+f"(d[2]), "+f"(d[3])
        : "r"(a[0]), "r"(a[1]), "r"(a[2]), "r"(a[3]), "r"(b0), "r"(b1));
}

__global__ __launch_bounds__(256, 3) void decoder_lds64_kernel(
    const float* __restrict__ dec_in, const float* __restrict__ s_in,
    const float* __restrict__ enc,    const float* __restrict__ W_attn,
    const float* __restrict__ b_attn, const float* __restrict__ v_attn,
    const float* __restrict__ W_emb,  const float* __restrict__ b_emb,
    const float* __restrict__ W_ih,   const float* __restrict__ W_hh,
    const float* __restrict__ b_ih,   const float* __restrict__ b_hh,
    const float* __restrict__ W_fc,   const float* __restrict__ b_fc,
    float* __restrict__ out, int write_h)
{
    extern __shared__ __align__(16) unsigned char sm[];
    float*    Asf    = (float*)(sm + OFF_A);
    uint32_t* Bs     = (uint32_t*)(sm + OFF_B);
    float*    part   = (float*)(sm + OFF_PART);
    float*    ctxp   = (float*)(sm + OFF_CTXP);
    float*    ctxa   = (float*)(sm + OFF_CTXA);
    float*    s_sm   = (float*)(sm + OFF_S);
    float*    pre_sm = (float*)(sm + OFF_PRE);
    float*    v_sm2  = (float*)(sm + OFF_V);
    float*    gh_sm  = (float*)(sm + OFF_GH);
    float*    gie_sm = (float*)(sm + OFF_GIE);
    float*    emb_sm = (float*)(sm + OFF_EMB);
    float*    red    = (float*)(sm + OFF_RED);
    float*    lsum   = (float*)(sm + OFF_LSUM);

    const int t    = threadIdx.x;
    const int b    = blockIdx.x;
    const int lane = t & 31;
    const int w    = t >> 5;
    const int qid  = lane >> 2;
    const int qtr  = lane & 3;
    const uint32_t su = smem_u32(sm);

    // staging map: thread covers rows rowg+16*it (it<4), 16-B segment seg
    const int rowg = t >> 4;            // 0..15
    const int seg  = t & 15;            // 0..15
    const float* gbase = enc + ((size_t)rowg * BB + b) * 64 + seg * 4;
    const uint32_t sbase = su + OFF_A + (rowg * ASTR + seg * 4) * 4;
    const size_t gstep = (size_t)16 * BB * 64;   // 16 rows

    // ---- prologue: chunk 0 in flight ----
    {
        const float* g = gbase;
        uint32_t s = sbase;
        #pragma unroll
        for (int it = 0; it < 4; ++it) {
            cpasync16(s, g);
            g += gstep;
            s += 16 * ASTR * 4;
        }
        cp_commit();
    }

    // ---- init / precompute (overlaps stream) ----
    if (t < 32) s_sm[t] = s_in[b * 32 + t];
    if (t < 16) {
        float e = W_emb[t] * dec_in[b] + b_emb[t];
        emb_sm[t] = e > 0.f ? e : 0.f;
    }
    for (int idx = t; idx < 2048; idx += 256) {
        int j = idx >> 6, k = idx & 63;
        Bs[k * BSTR + j] = f2tf32(W_attn[j * 96 + 32 + k]);
    }
    __syncthreads();

    if (t < 32) {
        float a = b_attn[t];
        #pragma unroll
        for (int m = 0; m < 32; ++m) a += W_attn[t * 96 + m] * s_sm[m];
        pre_sm[t] = a;
        v_sm2[t]  = v_attn[t];
    } else if (t < 128) {
        int g = t - 32;
        float a = b_hh[g];
        #pragma unroll
        for (int m = 0; m < 32; ++m) a += W_hh[g * 32 + m] * s_sm[m];
        gh_sm[g] = a;
    } else if (t < 224) {
        int g = t - 128;
        float a = b_ih[g];
        #pragma unroll
        for (int m = 0; m < 16; ++m) a += W_ih[g * 80 + m] * emb_sm[m];
        gie_sm[g] = a;
    }
    __syncthreads();

    // warp tiling: rows m0..m0+15, cols [nhalf*16, nhalf*16+16)
    const int m0 = (w & 3) * 16;
    const int nhalf = w >> 2;           // 0 or 1
    const int nt0 = nhalf * 2;
    const int barid = 1 + (w & 3);
    const int ctxrow0 = m0 + nhalf * 8; // this warp's 8 ctx/exp rows

    // B fragments, permuted-k: step ks slot qtr -> k=8ks+2qtr, slot qtr+4 -> +1
    uint32_t Br[2][8][2];
    #pragma unroll
    for (int i = 0; i < 2; ++i)
        #pragma unroll
        for (int ks = 0; ks < 8; ++ks) {
            int col = 8 * (nt0 + i) + qid;
            int k0  = 8 * ks + 2 * qtr;
            Br[i][ks][0] = Bs[k0       * BSTR + col];
            Br[i][ks][1] = Bs[(k0 + 1) * BSTR + col];
        }
    float preR[2][2], vR[2][2];
    #pragma unroll
    for (int i = 0; i < 2; ++i) {
        int c = (nt0 + i) * 8 + 2 * qtr;
        preR[i][0] = pre_sm[c];  preR[i][1] = pre_sm[c + 1];
        vR[i][0]   = v_sm2[c];   vR[i][1]   = v_sm2[c + 1];
    }

    const int arow0 = (m0 + qid)     * ASTR + 2 * qtr;
    const int arow1 = (m0 + 8 + qid) * ASTR + 2 * qtr;

    float cacc0 = 0.f, cacc1 = 0.f, l_acc = 0.f;

    // ---------------- pipelined chunk loop ----------------
    for (int ch = 0; ch < NCH; ++ch) {
        cp_wait0();
        __syncthreads();               // chunk ch visible; prior ctx reads done

        if (ch < NCH - 1) {
            const float* g = gbase + (size_t)(ch + 1) * SC * (BB * 64);
            uint32_t s = sbase + ((ch + 1) & 1) * ABYTES;
            #pragma unroll
            for (int it = 0; it < 4; ++it) {
                cpasync16(s, g);
                g += gstep;
                s += 16 * ASTR * 4;
            }
            cp_commit();
        }

        const float* A = Asf + (ch & 1) * (SC * ASTR);

        float D[2][4];
        #pragma unroll
        for (int i = 0; i < 2; ++i)
            #pragma unroll
            for (int k = 0; k < 4; ++k) D[i][k] = 0.f;

        // A frags: one LDS.64 per row per step (raw fp32 bits -> tf32 truncate)
        #pragma unroll
        for (int ks = 0; ks < 8; ++ks) {
            uint2 u0 = *(const uint2*)&A[arow0 + 8 * ks];
            uint2 u1 = *(const uint2*)&A[arow1 + 8 * ks];
            uint32_t a[4] = {u0.x, u1.x, u0.y, u1.y};
            mma_tf32(D[0], a, Br[0][ks][0], Br[0][ks][1]);
            mma_tf32(D[1], a, Br[1][ks][0], Br[1][ks][1]);
        }

        // half-logit partials over this warp's 16 cols
        float pl0 = 0.f, pl1 = 0.f;
        #pragma unroll
        for (int i = 0; i < 2; ++i) {
            pl0 += vR[i][0] * tanh_ap(D[i][0] + preR[i][0]);
            pl0 += vR[i][1] * tanh_ap(D[i][1] + preR[i][1]);
            pl1 += vR[i][0] * tanh_ap(D[i][2] + preR[i][0]);
            pl1 += vR[i][1] * tanh_ap(D[i][3] + preR[i][1]);
        }
        pl0 += __shfl_xor_sync(0xffffffffu, pl0, 1);
        pl0 += __shfl_xor_sync(0xffffffffu, pl0, 2);
        pl1 += __shfl_xor_sync(0xffffffffu, pl1, 1);
        pl1 += __shfl_xor_sync(0xffffffffu, pl1, 2);
        if (qtr == 0) {
            part[nhalf * 64 + m0 + qid]     = pl0;
            part[nhalf * 64 + m0 + 8 + qid] = pl1;
        }
        barpair(barid);    // pair (w, w+4) exchanged half-logits

        // exp once per row (lanes 0..7), broadcast via shuffle into ctx loop
        float pexp = 0.f;
        if (lane < 8) {
            int row = ctxrow0 + lane;
            pexp = __expf(part[row] + part[64 + row]);   // |logit| <= ~1.3, safe
            l_acc += pexp;
        }
        #pragma unroll
        for (int rr = 0; rr < 8; ++rr) {
            float ps = __shfl_sync(0xffffffffu, pexp, rr);
            float2 e2 = *(const float2*)&A[(ctxrow0 + rr) * ASTR + 2 * lane];
            cacc0 += ps * e2.x;
            cacc1 += ps * e2.y;
        }
    }

    // ---------------- reductions ----------------
    ctxp[w * 64 + 2 * lane]     = cacc0;
    ctxp[w * 64 + 2 * lane + 1] = cacc1;
    {
        float ws = l_acc;   // only lanes 0..7 nonzero
        #pragma unroll
        for (int off = 16; off > 0; off >>= 1)
            ws += __shfl_xor_sync(0xffffffffu, ws, off);
        if (lane == 0) red[w] = ws;
    }
    __syncthreads();
    if (t == 0)
        lsum[0] = red[0] + red[1] + red[2] + red[3] +
                  red[4] + red[5] + red[6] + red[7];
    __syncthreads();
    if (t < 64) {
        float c = 0.f;
        #pragma unroll
        for (int ww = 0; ww < 8; ++ww) c += ctxp[ww * 64 + t];
        ctxa[t] = c / lsum[0];
    }
    __syncthreads();

    // ---------------- GRU + fc (warp 0) ----------------
    if (w == 0) {
        int j = lane;
        float gir = gie_sm[j], giz = gie_sm[32 + j], gin = gie_sm[64 + j];
        const float* wr = W_ih + j        * 80 + 16;
        const float* wz = W_ih + (32 + j) * 80 + 16;
        const float* wn = W_ih + (64 + j) * 80 + 16;
        #pragma unroll 8
        for (int k2 = 0; k2 < 64; ++k2) {
            float c = ctxa[k2];
            gir += wr[k2] * c;
            giz += wz[k2] * c;
            gin += wn[k2] * c;
        }
        float r = sigm(gir + gh_sm[j]);
        float z = sigm(giz + gh_sm[32 + j]);
        float n = tanhf(gin + r * gh_sm[64 + j]);
        float h = (1.f - z) * n + z * s_sm[j];
        if (write_h) out[BB + b * 32 + j] = h;

        float contrib = h * W_fc[j]
                      + ctxa[2 * j]     * W_fc[32 + 2 * j]
                      + ctxa[2 * j + 1] * W_fc[33 + 2 * j];
        if (j < 16) contrib += emb_sm[j] * W_fc[96 + j];
        #pragma unroll
        for (int off = 16; off > 0; off >>= 1)
            contrib += __shfl_xor_sync(0xffffffffu, contrib, off);
        if (j == 0) out[b] = contrib + b_fc[0];
    }
}

extern "C" void kernel_launch(void* const* d_in, const int* in_sizes, int n_in,
                              void* d_out, int out_size) {
    const float* dec_in = (const float*)d_in[0];
    const float* s_in   = (const float*)d_in[1];
    const float* enc    = (const float*)d_in[2];
    const float* W_attn = (const float*)d_in[3];
    const float* b_attn = (const float*)d_in[4];
    const float* v_attn = (const float*)d_in[5];
    const float* W_emb  = (const float*)d_in[6];
    const float* b_emb  = (const float*)d_in[7];
    const float* W_ih   = (const float*)d_in[8];
    const float* W_hh   = (const float*)d_in[9];
    const float* b_ih   = (const float*)d_in[10];
    const float* b_hh   = (const float*)d_in[11];
    const float* W_fc   = (const float*)d_in[12];
    const float* b_fc   = (const float*)d_in[13];

    cudaFuncSetAttribute(decoder_lds64_kernel,
                         cudaFuncAttributeMaxDynamicSharedMemorySize, SMEM_SZ);
    int write_h = (out_size >= BB * 33) ? 1 : 0;
    decoder_lds64_kernel<<<BB, 256, SMEM_SZ>>>(dec_in, s_in, enc, W_attn, b_attn, v_attn,
                                               W_emb, b_emb, W_ih, W_hh, b_ih, b_hh,
                                               W_fc, b_fc, (float*)d_out, write_h);
}